// round 3
// baseline (speedup 1.0000x reference)
#include <cuda_runtime.h>
#include <math.h>

// ---------------- Problem constants ----------------
#define B_    2
#define S_    2048
#define H_    2048
#define NH_   16
#define QL    1536
#define KVL   512
#define DN    128
#define DR    64
#define DV    128
#define DQK   192           // 192
#define BS_   (B_ * S_)     // 4096

// ---------------- Device scratch (static: no allocs allowed) ----------------
__device__ float g_qlat[BS_ * QL];                         // 4096 x 1536
__device__ float g_kva [BS_ * (KVL + DR)];                 // 4096 x 576
__device__ float g_q   [BS_ * NH_ * DQK];                  // 4096 x 3072
__device__ float g_kvx [(size_t)BS_ * NH_ * (DN + DV)];    // 4096 x 4096
__device__ float g_kf  [BS_ * NH_ * DQK];                  // 4096 x 3072
__device__ float g_scores[(size_t)B_ * NH_ * S_ * S_];     // 512 MB
__device__ float g_attn[BS_ * NH_ * DV];                   // 4096 x 2048
__device__ float g_cos [S_ * (DR / 2)];
__device__ float g_sin [S_ * (DR / 2)];

// ---------------- Generic tiled SGEMM ----------------
// BT = true : C = A * B^T, B is [N, K] row-major (weights / NT form)
// BT = false: C = A * B,   B is [K, N] row-major (NN form, for P@V)
// 128x128 tile, BK=8, 256 threads, 8x8 per-thread microtile, double-buffered.
// z-batched: blockIdx.z -> (zb = z/NH, zh = z%NH) with independent strides.
template <bool BT>
__global__ void __launch_bounds__(256)
sgemm_kernel(const float* __restrict__ A, const float* __restrict__ Bm,
             float* __restrict__ C,
             int M, int N, int K, int lda, int ldb, int ldc,
             long long aSb, long long aSh, long long bSb, long long bSh,
             long long cSb, long long cSh, float alpha)
{
    __shared__ float As[2][8][128];
    __shared__ float Bs[2][8][128];

    const int z  = blockIdx.z;
    const int zb = z >> 4;      // NH_ == 16
    const int zh = z & 15;
    A  += (long long)zb * aSb + (long long)zh * aSh;
    Bm += (long long)zb * bSb + (long long)zh * bSh;
    C  += (long long)zb * cSb + (long long)zh * cSh;

    const int tid = threadIdx.x;
    const int bm = blockIdx.y << 7;
    const int bn = blockIdx.x << 7;

    // A load lane: row = bm + (tid>>1), k-offset = (tid&1)*4
    const int lr = tid >> 1;
    const int lk = (tid & 1) << 2;
    const int arow = bm + lr;
    const bool aval = arow < M;
    const long long abase = (long long)arow * lda + lk;

    // B load lane
    long long bbase = 0;
    bool bval = false;
    int bkk = 0, bnn = 0;
    if (BT) {
        const int brow = bn + lr;
        bval  = brow < N;
        bbase = (long long)brow * ldb + lk;
    } else {
        bkk  = tid >> 5;          // 0..7   (k row)
        bnn  = (tid & 31) << 2;   // 0..124 (n offset)
        bval = (bn + bnn) < N;
        bbase = (long long)bkk * ldb + bn + bnn;
    }

    const int ty = tid >> 4, tx = tid & 15;
    float acc[8][8];
#pragma unroll
    for (int i = 0; i < 8; i++)
#pragma unroll
        for (int j = 0; j < 8; j++) acc[i][j] = 0.f;

    const float4 f4z = make_float4(0.f, 0.f, 0.f, 0.f);

    // ---- stage 0 ----
    {
        float4 a = aval ? *(const float4*)(A + abase) : f4z;
        As[0][lk + 0][lr] = a.x; As[0][lk + 1][lr] = a.y;
        As[0][lk + 2][lr] = a.z; As[0][lk + 3][lr] = a.w;
        float4 b = bval ? *(const float4*)(Bm + bbase) : f4z;
        if (BT) {
            Bs[0][lk + 0][lr] = b.x; Bs[0][lk + 1][lr] = b.y;
            Bs[0][lk + 2][lr] = b.z; Bs[0][lk + 3][lr] = b.w;
        } else {
            *(float4*)&Bs[0][bkk][bnn] = b;
        }
    }
    __syncthreads();

    const int nk = K >> 3;
    for (int kt = 0; kt < nk; kt++) {
        const int cur = kt & 1;
        float4 aN = f4z, bN = f4z;
        const bool have = (kt + 1) < nk;
        if (have) {
            const long long koff = (long long)(kt + 1) << 3;
            aN = aval ? *(const float4*)(A + abase + koff) : f4z;
            if (BT) bN = bval ? *(const float4*)(Bm + bbase + koff) : f4z;
            else    bN = bval ? *(const float4*)(Bm + bbase + koff * ldb) : f4z;
        }
#pragma unroll
        for (int k = 0; k < 8; k++) {
            float4 a0 = *(const float4*)&As[cur][k][(ty << 3) + 0];
            float4 a1 = *(const float4*)&As[cur][k][(ty << 3) + 4];
            float4 b0 = *(const float4*)&Bs[cur][k][(tx << 3) + 0];
            float4 b1 = *(const float4*)&Bs[cur][k][(tx << 3) + 4];
            float av[8] = {a0.x, a0.y, a0.z, a0.w, a1.x, a1.y, a1.z, a1.w};
            float bv[8] = {b0.x, b0.y, b0.z, b0.w, b1.x, b1.y, b1.z, b1.w};
#pragma unroll
            for (int i = 0; i < 8; i++)
#pragma unroll
                for (int j = 0; j < 8; j++)
                    acc[i][j] += av[i] * bv[j];
        }
        if (have) {
            const int nxt = cur ^ 1;
            As[nxt][lk + 0][lr] = aN.x; As[nxt][lk + 1][lr] = aN.y;
            As[nxt][lk + 2][lr] = aN.z; As[nxt][lk + 3][lr] = aN.w;
            if (BT) {
                Bs[nxt][lk + 0][lr] = bN.x; Bs[nxt][lk + 1][lr] = bN.y;
                Bs[nxt][lk + 2][lr] = bN.z; Bs[nxt][lk + 3][lr] = bN.w;
            } else {
                *(float4*)&Bs[nxt][bkk][bnn] = bN;
            }
        }
        __syncthreads();
    }

    // ---- epilogue ----
#pragma unroll
    for (int i = 0; i < 8; i++) {
        const int r = bm + (ty << 3) + i;
        if (r < M) {
#pragma unroll
            for (int j = 0; j < 8; j += 4) {
                const int c = bn + (tx << 3) + j;
                if (c + 3 < N) {
                    float4 o;
                    o.x = alpha * acc[i][j + 0];
                    o.y = alpha * acc[i][j + 1];
                    o.z = alpha * acc[i][j + 2];
                    o.w = alpha * acc[i][j + 3];
                    *(float4*)(C + (long long)r * ldc + c) = o;
                } else {
#pragma unroll
                    for (int jj = 0; jj < 4; jj++)
                        if (c + jj < N)
                            C[(long long)r * ldc + c + jj] = alpha * acc[i][j + jj];
                }
            }
        }
    }
}

// ---------------- RMSNorm (rows) ----------------
__global__ void __launch_bounds__(256)
rmsnorm_kernel(float* __restrict__ X, const float* __restrict__ W, int n, int ld)
{
    float* row = X + (size_t)blockIdx.x * ld;
    const int tid = threadIdx.x;
    float ss = 0.f;
    for (int i = tid; i < n; i += 256) {
        float x = row[i];
        ss += x * x;
    }
#pragma unroll
    for (int o = 16; o; o >>= 1) ss += __shfl_xor_sync(0xffffffffu, ss, o);
    __shared__ float red[8];
    if ((tid & 31) == 0) red[tid >> 5] = ss;
    __syncthreads();
    float tot = red[0];
#pragma unroll
    for (int w = 1; w < 8; w++) tot += red[w];
    const float inv = 1.f / sqrtf(tot / (float)n + 1e-6f);
    for (int i = tid; i < n; i += 256)
        row[i] = W[i] * row[i] * inv;
}

// ---------------- RoPE freqs table (fp64, matches numpy) ----------------
__global__ void freqs_kernel()
{
    const int pos = blockIdx.x;   // 0..S_-1
    const int i   = threadIdx.x;  // 0..31
    const double inv = pow(10000.0, -(double)((float)(2 * i) / (float)DR));
    const double f   = (double)pos * inv;
    g_cos[pos * (DR / 2) + i] = (float)cos(f);
    g_sin[pos * (DR / 2) + i] = (float)sin(f);
}

// ---------------- RoPE on k_pe (in g_kva cols 512..575) ----------------
__global__ void rope_k_kernel(float* __restrict__ kva)
{
    const int row = blockIdx.x;
    const int i   = threadIdx.x;       // pair 0..31
    const int pos = row & (S_ - 1);
    const float c = g_cos[pos * 32 + i];
    const float s = g_sin[pos * 32 + i];
    float* p = kva + (size_t)row * (KVL + DR) + KVL + 2 * i;
    const float e = p[0], o = p[1];
    p[0] = e * c - o * s;
    p[1] = e * s + o * c;
}

// ---------------- RoPE on q_pe (g_q cols h*192+128 .. +191) ----------------
__global__ void __launch_bounds__(512)
rope_q_kernel(float* __restrict__ q)
{
    const int row = blockIdx.x;
    const int h   = threadIdx.x >> 5;
    const int i   = threadIdx.x & 31;
    const int pos = row & (S_ - 1);
    const float c = g_cos[pos * 32 + i];
    const float s = g_sin[pos * 32 + i];
    float* p = q + (size_t)row * (NH_ * DQK) + h * DQK + DN + 2 * i;
    const float e = p[0], o = p[1];
    p[0] = e * c - o * s;
    p[1] = e * s + o * c;
}

// ---------------- Assemble full K: kf[row][h*192+d] ----------------
__global__ void __launch_bounds__(256)
build_kf_kernel(const float* __restrict__ kvx, const float* __restrict__ kva,
                float* __restrict__ kf)
{
    const int row = blockIdx.x;
    for (int idx = threadIdx.x; idx < NH_ * DQK; idx += 256) {
        const int h = idx / DQK, d = idx % DQK;
        float v;
        if (d < DN) v = kvx[(size_t)row * (NH_ * (DN + DV)) + h * (DN + DV) + d];
        else        v = kva[(size_t)row * (KVL + DR) + KVL + (d - DN)];
        kf[(size_t)row * (NH_ * DQK) + idx] = v;
    }
}

// ---------------- Row softmax, n = 2048 fixed ----------------
__global__ void __launch_bounds__(256)
softmax_kernel(float* __restrict__ P)
{
    float* row = P + (size_t)blockIdx.x * S_;
    const int tid = threadIdx.x;
    float v[8];
#pragma unroll
    for (int k = 0; k < 8; k++) v[k] = row[tid + k * 256];
    float m = v[0];
#pragma unroll
    for (int k = 1; k < 8; k++) m = fmaxf(m, v[k]);
#pragma unroll
    for (int o = 16; o; o >>= 1) m = fmaxf(m, __shfl_xor_sync(0xffffffffu, m, o));
    __shared__ float red[8];
    if ((tid & 31) == 0) red[tid >> 5] = m;
    __syncthreads();
    float mm = red[0];
#pragma unroll
    for (int w = 1; w < 8; w++) mm = fmaxf(mm, red[w]);
    __syncthreads();                    // protect red[] before reuse
    float s = 0.f;
#pragma unroll
    for (int k = 0; k < 8; k++) {
        v[k] = __expf(v[k] - mm);
        s += v[k];
    }
#pragma unroll
    for (int o = 16; o; o >>= 1) s += __shfl_xor_sync(0xffffffffu, s, o);
    if ((tid & 31) == 0) red[tid >> 5] = s;
    __syncthreads();
    float tot = red[0];
#pragma unroll
    for (int w = 1; w < 8; w++) tot += red[w];
    const float inv = 1.f / tot;
#pragma unroll
    for (int k = 0; k < 8; k++) row[tid + k * 256] = v[k] * inv;
}

// ---------------- Host launch ----------------
static inline void launch_nt(const float* A, const float* Bw, float* C,
                             int M, int N, int K, int lda, int ldb, int ldc,
                             long long aSb, long long aSh, long long bSb, long long bSh,
                             long long cSb, long long cSh, int gz, float alpha)
{
    dim3 grid((N + 127) / 128, (M + 127) / 128, gz);
    sgemm_kernel<true><<<grid, 256>>>(A, Bw, C, M, N, K, lda, ldb, ldc,
                                      aSb, aSh, bSb, bSh, cSb, cSh, alpha);
}

static inline void launch_nn(const float* A, const float* Bw, float* C,
                             int M, int N, int K, int lda, int ldb, int ldc,
                             long long aSb, long long aSh, long long bSb, long long bSh,
                             long long cSb, long long cSh, int gz, float alpha)
{
    dim3 grid((N + 127) / 128, (M + 127) / 128, gz);
    sgemm_kernel<false><<<grid, 256>>>(A, Bw, C, M, N, K, lda, ldb, ldc,
                                       aSb, aSh, bSb, bSh, cSb, cSh, alpha);
}

extern "C" void kernel_launch(void* const* d_in, const int* in_sizes, int n_in,
                              void* d_out, int out_size)
{
    (void)in_sizes; (void)n_in; (void)out_size;
    const float* hidden    = (const float*)d_in[0];
    const float* wq_a      = (const float*)d_in[1];
    const float* q_norm_w  = (const float*)d_in[2];
    const float* wq_b      = (const float*)d_in[3];
    const float* wkv_a     = (const float*)d_in[4];
    const float* kv_norm_w = (const float*)d_in[5];
    const float* wkv_b     = (const float*)d_in[6];
    const float* wo        = (const float*)d_in[7];
    float* out = (float*)d_out;

    float *qlat, *kva, *q, *kvx, *kf, *scores, *attn;
    cudaGetSymbolAddress((void**)&qlat,   g_qlat);
    cudaGetSymbolAddress((void**)&kva,    g_kva);
    cudaGetSymbolAddress((void**)&q,      g_q);
    cudaGetSymbolAddress((void**)&kvx,    g_kvx);
    cudaGetSymbolAddress((void**)&kf,     g_kf);
    cudaGetSymbolAddress((void**)&scores, g_scores);
    cudaGetSymbolAddress((void**)&attn,   g_attn);

    const float SCALE = (float)(1.0 / sqrt((double)DQK));

    // RoPE tables
    freqs_kernel<<<S_, 32>>>();

    // 1) q_lat = hidden @ wq_a^T       [4096, 1536]
    launch_nt(hidden, wq_a, qlat, BS_, QL, H_, H_, H_, QL, 0,0,0,0,0,0, 1, 1.f);
    // 2) kva = hidden @ wkv_a^T        [4096, 576]
    launch_nt(hidden, wkv_a, kva, BS_, KVL + DR, H_, H_, H_, KVL + DR, 0,0,0,0,0,0, 1, 1.f);
    // 3) rmsnorm q_lat
    rmsnorm_kernel<<<BS_, 256>>>(qlat, q_norm_w, QL, QL);
    // 4) rmsnorm kv_c (first 512 cols of kva)
    rmsnorm_kernel<<<BS_, 256>>>(kva, kv_norm_w, KVL, KVL + DR);
    // 5) RoPE k_pe in-place
    rope_k_kernel<<<BS_, 32>>>(kva);
    // 6) q = q_lat @ wq_b^T            [4096, 3072]
    launch_nt(qlat, wq_b, q, BS_, NH_ * DQK, QL, QL, QL, NH_ * DQK, 0,0,0,0,0,0, 1, 1.f);
    // 7) kv_x = kv_c @ wkv_b^T         [4096, 4096]  (A row stride 576, use 512 cols)
    launch_nt(kva, wkv_b, kvx, BS_, NH_ * (DN + DV), KVL, KVL + DR, KVL,
              NH_ * (DN + DV), 0,0,0,0,0,0, 1, 1.f);
    // 8) RoPE q_pe in-place
    rope_q_kernel<<<BS_, 512>>>(q);
    // 9) assemble kf
    build_kf_kernel<<<BS_, 256>>>(kvx, kva, kf);
    // 10) scores[z][q][k] = SCALE * qf . kf   (batched over z = b*16+h)
    launch_nt(q, kf, scores, S_, S_, DQK,
              NH_ * DQK, NH_ * DQK, S_,
              (long long)S_ * NH_ * DQK, DQK,
              (long long)S_ * NH_ * DQK, DQK,
              (long long)NH_ * S_ * S_, (long long)S_ * S_,
              B_ * NH_, SCALE);
    // 11) softmax rows
    softmax_kernel<<<B_ * NH_ * S_, 256>>>(scores);
    // 12) attn[row][h*128+c] = P @ V  (V = kvx cols h*256+128..255)
    launch_nn(scores, kvx + DN, attn, S_, DV, S_,
              S_, NH_ * (DN + DV), NH_ * DV,
              (long long)NH_ * S_ * S_, (long long)S_ * S_,
              (long long)S_ * NH_ * (DN + DV), (long long)(DN + DV),
              (long long)S_ * NH_ * DV, (long long)DV,
              B_ * NH_, 1.f);
    // 13) out = attn @ wo^T            [4096, 2048]
    launch_nt(attn, wo, out, BS_, H_, NH_ * DV, NH_ * DV, NH_ * DV, H_,
              0,0,0,0,0,0, 1, 1.f);
}

// round 5
// speedup vs baseline: 2.3290x; 2.3290x over previous
#include <cuda_runtime.h>
#include <cuda_bf16.h>
#include <math.h>
#include <stdint.h>

// ---------------- Problem constants ----------------
#define B_    2
#define S_    2048
#define H_    2048
#define NH_   16
#define QL    1536
#define KVL   512
#define DN    128
#define DR    64
#define DV    128
#define DQK   192
#define BS_   (B_ * S_)     // 4096

typedef __nv_bfloat16 bf16;

// ---------------- Device scratch (static: no allocs allowed) ----------------
// fp32 intermediates
__device__ float g_qlat[BS_ * QL];
__device__ float g_kva [BS_ * (KVL + DR)];
__device__ float g_q   [BS_ * NH_ * DQK];
__device__ float g_kvx [(size_t)BS_ * NH_ * (DN + DV)];
__device__ float g_scores[(size_t)B_ * NH_ * S_ * S_];     // 512 MB
__device__ float g_attn[BS_ * NH_ * DV];
__device__ float g_cos [S_ * (DR / 2)];
__device__ float g_sin [S_ * (DR / 2)];

// split bf16 operand copies (hi / lo)
__device__ bf16 g_hid_h [(size_t)BS_ * H_],            g_hid_l [(size_t)BS_ * H_];
__device__ bf16 g_wqa_h [(size_t)QL * H_],             g_wqa_l [(size_t)QL * H_];
__device__ bf16 g_wqb_h [(size_t)NH_ * DQK * QL],      g_wqb_l [(size_t)NH_ * DQK * QL];
__device__ bf16 g_wkva_h[(size_t)(KVL + DR) * H_],     g_wkva_l[(size_t)(KVL + DR) * H_];
__device__ bf16 g_wkvb_h[(size_t)NH_ * (DN + DV) * KVL], g_wkvb_l[(size_t)NH_ * (DN + DV) * KVL];
__device__ bf16 g_wo_h  [(size_t)H_ * NH_ * DV],       g_wo_l  [(size_t)H_ * NH_ * DV];
__device__ bf16 g_qlat_h[(size_t)BS_ * QL],            g_qlat_l[(size_t)BS_ * QL];
__device__ bf16 g_kva_h [(size_t)BS_ * (KVL + DR)],    g_kva_l [(size_t)BS_ * (KVL + DR)];
__device__ bf16 g_qs_h  [(size_t)BS_ * NH_ * DQK],     g_qs_l  [(size_t)BS_ * NH_ * DQK];
__device__ bf16 g_kf_h  [(size_t)BS_ * NH_ * DQK],     g_kf_l  [(size_t)BS_ * NH_ * DQK];
__device__ bf16 g_P_h   [(size_t)B_ * NH_ * S_ * S_],  g_P_l   [(size_t)B_ * NH_ * S_ * S_];
__device__ bf16 g_vt_h  [(size_t)B_ * NH_ * DV * S_],  g_vt_l  [(size_t)B_ * NH_ * DV * S_];
__device__ bf16 g_attn_h[(size_t)BS_ * NH_ * DV],      g_attn_l[(size_t)BS_ * NH_ * DV];

// ---------------- helpers ----------------
__device__ __forceinline__ uint32_t smem_u32(const void* p) {
    uint32_t a;
    asm("{ .reg .u64 t; cvta.to.shared.u64 t, %1; cvt.u32.u64 %0, t; }" : "=r"(a) : "l"(p));
    return a;
}

__device__ __forceinline__ void splitf(float x, bf16& h, bf16& l) {
    h = __float2bfloat16_rn(x);
    l = __float2bfloat16_rn(x - __bfloat162float(h));
}

__device__ __forceinline__ void ldsm_x4(uint32_t r[4], uint32_t addr) {
    asm volatile("ldmatrix.sync.aligned.m8n8.x4.shared.b16 {%0,%1,%2,%3}, [%4];"
                 : "=r"(r[0]), "=r"(r[1]), "=r"(r[2]), "=r"(r[3]) : "r"(addr));
}

__device__ __forceinline__ void mma16816(float* c, const uint32_t a[4],
                                         uint32_t b0, uint32_t b1) {
    asm volatile(
        "mma.sync.aligned.m16n8k16.row.col.f32.bf16.bf16.f32 "
        "{%0,%1,%2,%3}, {%4,%5,%6,%7}, {%8,%9}, {%0,%1,%2,%3};"
        : "+f"(c[0]), "+f"(c[1]), "+f"(c[2]), "+f"(c[3])
        : "r"(a[0]), "r"(a[1]), "r"(a[2]), "r"(a[3]), "r"(b0), "r"(b1));
}

// ---------------- split-bf16 HMMA GEMM: C = alpha * A(MxK) . B(NxK)^T ----------------
// 128x128x32 block tile, 8 warps (2x4), 64x32 warp tile, double-buffered smem.
// smem row = 32 bf16 padded to 80 bytes (stride 5*16B -> conflict-free ldmatrix).
#define ROWB   80
#define MATB   (128 * ROWB)       // 10240 B per matrix
#define STAGEB (4 * MATB)         // 40960 B : Ah, Al, Bh, Bl

__global__ void __launch_bounds__(256, 1)
mma_gemm(const bf16* __restrict__ Ah, const bf16* __restrict__ Al,
         const bf16* __restrict__ Bh, const bf16* __restrict__ Bl,
         float* __restrict__ C,
         int M, int N, int K, int lda, int ldb, int ldc,
         long long aSb, long long aSh, long long bSb, long long bSh,
         long long cSb, long long cSh, float alpha)
{
    extern __shared__ char sm[];
    const uint32_t sbase = smem_u32(sm);

    const int tid  = threadIdx.x;
    const int wid  = tid >> 5;
    const int lane = tid & 31;

    const int z  = blockIdx.z;
    const int zb = z >> 4, zh = z & 15;
    Ah += (long long)zb * aSb + (long long)zh * aSh;
    Al += (long long)zb * aSb + (long long)zh * aSh;
    Bh += (long long)zb * bSb + (long long)zh * bSh;
    Bl += (long long)zb * bSb + (long long)zh * bSh;
    C  += (long long)zb * cSb + (long long)zh * cSh;

    const int bm = blockIdx.y << 7;
    const int bn = blockIdx.x << 7;

    const int wm = (wid >> 2) * 64;   // warp row offset
    const int wn = (wid & 3) * 32;    // warp col offset

    // loader lanes: each thread loads 2 adjacent 16B chunks per matrix
    const int lrow = tid >> 1;                 // 0..127
    const int lch  = (tid & 1) * 2;            // chunk base 0 or 2
    const long long agm = (long long)(bm + lrow) * lda + lch * 8;
    const int brow = bn + lrow;
    const bool bok = brow < N;
    const long long bgm = (long long)brow * ldb + lch * 8;
    const uint32_t s_off = (uint32_t)(lrow * ROWB + lch * 16);

    // ldmatrix per-lane offsets
    const uint32_t a_off = (uint32_t)((lane & 15) * ROWB + (lane >> 4) * 16);
    const uint32_t b_off = (uint32_t)(((lane & 7) + (lane >> 4) * 8) * ROWB + ((lane >> 3) & 1) * 16);

    float acc[4][4][4];
#pragma unroll
    for (int mt = 0; mt < 4; mt++)
#pragma unroll
        for (int nt = 0; nt < 4; nt++)
#pragma unroll
            for (int i = 0; i < 4; i++) acc[mt][nt][i] = 0.f;

    const uint4 z4 = make_uint4(0u, 0u, 0u, 0u);

    // prologue: stage 0
    {
        uint4 vah0 = *(const uint4*)(Ah + agm);
        uint4 vah1 = *(const uint4*)(Ah + agm + 8);
        uint4 val0 = *(const uint4*)(Al + agm);
        uint4 val1 = *(const uint4*)(Al + agm + 8);
        uint4 vbh0 = bok ? *(const uint4*)(Bh + bgm)     : z4;
        uint4 vbh1 = bok ? *(const uint4*)(Bh + bgm + 8) : z4;
        uint4 vbl0 = bok ? *(const uint4*)(Bl + bgm)     : z4;
        uint4 vbl1 = bok ? *(const uint4*)(Bl + bgm + 8) : z4;
        char* st = sm;
        *(uint4*)(st + s_off)               = vah0;
        *(uint4*)(st + s_off + 16)          = vah1;
        *(uint4*)(st + MATB + s_off)        = val0;
        *(uint4*)(st + MATB + s_off + 16)   = val1;
        *(uint4*)(st + 2*MATB + s_off)      = vbh0;
        *(uint4*)(st + 2*MATB + s_off + 16) = vbh1;
        *(uint4*)(st + 3*MATB + s_off)      = vbl0;
        *(uint4*)(st + 3*MATB + s_off + 16) = vbl1;
    }
    __syncthreads();

    const int nk = K >> 5;
    for (int kt = 0; kt < nk; kt++) {
        const int cur = kt & 1;
        // prefetch next k-tile into regs
        uint4 vah0, vah1, val0, val1, vbh0, vbh1, vbl0, vbl1;
        const bool have = (kt + 1) < nk;
        if (have) {
            const long long ko = (long long)(kt + 1) * 32;
            vah0 = *(const uint4*)(Ah + agm + ko);
            vah1 = *(const uint4*)(Ah + agm + ko + 8);
            val0 = *(const uint4*)(Al + agm + ko);
            val1 = *(const uint4*)(Al + agm + ko + 8);
            vbh0 = bok ? *(const uint4*)(Bh + bgm + ko)     : z4;
            vbh1 = bok ? *(const uint4*)(Bh + bgm + ko + 8) : z4;
            vbl0 = bok ? *(const uint4*)(Bl + bgm + ko)     : z4;
            vbl1 = bok ? *(const uint4*)(Bl + bgm + ko + 8) : z4;
        }
        // compute on stage cur
        {
            const uint32_t stA  = sbase + cur * STAGEB;
            const uint32_t stAl = stA + MATB;
            const uint32_t stB  = stA + 2 * MATB;
            const uint32_t stBl = stA + 3 * MATB;
#pragma unroll
            for (int km = 0; km < 2; km++) {
                const uint32_t kb = km * 32;
                uint32_t ah[4][4], al[4][4];
#pragma unroll
                for (int mt = 0; mt < 4; mt++) {
                    ldsm_x4(ah[mt], stA  + (uint32_t)((wm + mt * 16) * ROWB) + kb + a_off);
                    ldsm_x4(al[mt], stAl + (uint32_t)((wm + mt * 16) * ROWB) + kb + a_off);
                }
                uint32_t bh[2][4], bl[2][4];
#pragma unroll
                for (int bt = 0; bt < 2; bt++) {
                    ldsm_x4(bh[bt], stB  + (uint32_t)((wn + bt * 16) * ROWB) + kb + b_off);
                    ldsm_x4(bl[bt], stBl + (uint32_t)((wn + bt * 16) * ROWB) + kb + b_off);
                }
#pragma unroll
                for (int mt = 0; mt < 4; mt++)
#pragma unroll
                    for (int nt = 0; nt < 4; nt++) {
                        const int bt = nt >> 1, bi = (nt & 1) * 2;
                        mma16816(acc[mt][nt], ah[mt], bh[bt][bi], bh[bt][bi + 1]);
                        mma16816(acc[mt][nt], al[mt], bh[bt][bi], bh[bt][bi + 1]);
                        mma16816(acc[mt][nt], ah[mt], bl[bt][bi], bl[bt][bi + 1]);
                    }
            }
        }
        // store prefetched into other stage
        if (have) {
            char* st = sm + (cur ^ 1) * STAGEB;
            *(uint4*)(st + s_off)               = vah0;
            *(uint4*)(st + s_off + 16)          = vah1;
            *(uint4*)(st + MATB + s_off)        = val0;
            *(uint4*)(st + MATB + s_off + 16)   = val1;
            *(uint4*)(st + 2*MATB + s_off)      = vbh0;
            *(uint4*)(st + 2*MATB + s_off + 16) = vbh1;
            *(uint4*)(st + 3*MATB + s_off)      = vbl0;
            *(uint4*)(st + 3*MATB + s_off + 16) = vbl1;
        }
        __syncthreads();
    }

    // epilogue
    const int erow = lane >> 2;
    const int ecol = (lane & 3) * 2;
#pragma unroll
    for (int mt = 0; mt < 4; mt++) {
        const int r0 = bm + wm + mt * 16 + erow;
#pragma unroll
        for (int nt = 0; nt < 4; nt++) {
            const int c = bn + wn + nt * 8 + ecol;
            if (c < N) {
                float2 v0 = make_float2(alpha * acc[mt][nt][0], alpha * acc[mt][nt][1]);
                float2 v1 = make_float2(alpha * acc[mt][nt][2], alpha * acc[mt][nt][3]);
                *(float2*)(C + (long long)r0 * ldc + c)       = v0;
                *(float2*)(C + (long long)(r0 + 8) * ldc + c) = v1;
            }
        }
    }
}

#define GEMM_SMEM (2 * STAGEB)   // 81920 B

// ---------------- split kernel: fp32 -> (hi, lo) bf16 ----------------
__global__ void __launch_bounds__(256)
split_kernel(const float* __restrict__ s, bf16* __restrict__ h, bf16* __restrict__ l,
             long long n)
{
    const long long i = ((long long)blockIdx.x * 256 + threadIdx.x) * 4;
    if (i >= n) return;
    float4 v = *(const float4*)(s + i);
    bf16 hh[4], ll[4];
    splitf(v.x, hh[0], ll[0]); splitf(v.y, hh[1], ll[1]);
    splitf(v.z, hh[2], ll[2]); splitf(v.w, hh[3], ll[3]);
    uint2 ph, pl;
    __nv_bfloat162 h01 = __halves2bfloat162(hh[0], hh[1]), h23 = __halves2bfloat162(hh[2], hh[3]);
    __nv_bfloat162 l01 = __halves2bfloat162(ll[0], ll[1]), l23 = __halves2bfloat162(ll[2], ll[3]);
    ph.x = *(uint32_t*)&h01; ph.y = *(uint32_t*)&h23;
    pl.x = *(uint32_t*)&l01; pl.y = *(uint32_t*)&l23;
    *(uint2*)(h + i) = ph;
    *(uint2*)(l + i) = pl;
}

static inline void launch_split(const float* s, bf16* h, bf16* l, long long n)
{
    const long long blocks = (n / 4 + 255) / 256;
    split_kernel<<<(unsigned)blocks, 256>>>(s, h, l, n);
}

// ---------------- RMSNorm ----------------
__global__ void __launch_bounds__(256)
rmsnorm_kernel(float* __restrict__ X, const float* __restrict__ W, int n, int ld)
{
    float* row = X + (size_t)blockIdx.x * ld;
    const int tid = threadIdx.x;
    float ss = 0.f;
    for (int i = tid; i < n; i += 256) { float x = row[i]; ss += x * x; }
#pragma unroll
    for (int o = 16; o; o >>= 1) ss += __shfl_xor_sync(0xffffffffu, ss, o);
    __shared__ float red[8];
    if ((tid & 31) == 0) red[tid >> 5] = ss;
    __syncthreads();
    float tot = red[0];
#pragma unroll
    for (int w = 1; w < 8; w++) tot += red[w];
    const float inv = 1.f / sqrtf(tot / (float)n + 1e-6f);
    for (int i = tid; i < n; i += 256) row[i] = W[i] * row[i] * inv;
}

// ---------------- RoPE tables / kernels ----------------
__global__ void freqs_kernel()
{
    const int pos = blockIdx.x;
    const int i   = threadIdx.x;
    const double inv = pow(10000.0, -(double)((float)(2 * i) / (float)DR));
    const double f   = (double)pos * inv;
    g_cos[pos * (DR / 2) + i] = (float)cos(f);
    g_sin[pos * (DR / 2) + i] = (float)sin(f);
}

__global__ void rope_k_kernel(float* __restrict__ kva)
{
    const int row = blockIdx.x;
    const int i   = threadIdx.x;
    const int pos = row & (S_ - 1);
    const float c = g_cos[pos * 32 + i];
    const float s = g_sin[pos * 32 + i];
    float* p = kva + (size_t)row * (KVL + DR) + KVL + 2 * i;
    const float e = p[0], o = p[1];
    p[0] = e * c - o * s;
    p[1] = e * s + o * c;
}

__global__ void __launch_bounds__(512)
rope_q_kernel(float* __restrict__ q)
{
    const int row = blockIdx.x;
    const int h   = threadIdx.x >> 5;
    const int i   = threadIdx.x & 31;
    const int pos = row & (S_ - 1);
    const float c = g_cos[pos * 32 + i];
    const float s = g_sin[pos * 32 + i];
    float* p = q + (size_t)row * (NH_ * DQK) + h * DQK + DN + 2 * i;
    const float e = p[0], o = p[1];
    p[0] = e * c - o * s;
    p[1] = e * s + o * c;
}

// ---------------- Assemble K (split bf16 out) ----------------
__global__ void __launch_bounds__(256)
build_kf_kernel(const float* __restrict__ kvx, const float* __restrict__ kva,
                bf16* __restrict__ kfh, bf16* __restrict__ kfl)
{
    const int row = blockIdx.x;
    for (int idx = threadIdx.x; idx < NH_ * DQK; idx += 256) {
        const int h = idx / DQK, d = idx % DQK;
        float v;
        if (d < DN) v = kvx[(size_t)row * (NH_ * (DN + DV)) + h * (DN + DV) + d];
        else        v = kva[(size_t)row * (KVL + DR) + KVL + (d - DN)];
        bf16 hi, lo; splitf(v, hi, lo);
        kfh[(size_t)row * (NH_ * DQK) + idx] = hi;
        kfl[(size_t)row * (NH_ * DQK) + idx] = lo;
    }
}

// ---------------- V transpose (split bf16 out) ----------------
__global__ void __launch_bounds__(256)
transpose_v_kernel(const float* __restrict__ kvx, bf16* __restrict__ vth,
                   bf16* __restrict__ vtl)
{
    __shared__ float t[32][33];
    const int z = blockIdx.z;
    const int b = z >> 4, h = z & 15;
    const int k0 = blockIdx.x * 32, n0 = blockIdx.y * 32;
    const int tx = threadIdx.x, ty = threadIdx.y;   // 32x8
    const float* src = kvx + ((size_t)(b * S_ + k0 + ty)) * (NH_ * (DN + DV))
                     + h * (DN + DV) + DN + n0 + tx;
#pragma unroll
    for (int i = 0; i < 32; i += 8)
        t[ty + i][tx] = src[(size_t)i * (NH_ * (DN + DV))];
    __syncthreads();
#pragma unroll
    for (int i = 0; i < 32; i += 8) {
        float v = t[tx][ty + i];
        bf16 hi, lo; splitf(v, hi, lo);
        const size_t di = ((size_t)z * DV + n0 + ty + i) * S_ + k0 + tx;
        vth[di] = hi;
        vtl[di] = lo;
    }
}

// ---------------- Row softmax (fp32 in, split bf16 out) ----------------
__global__ void __launch_bounds__(256)
softmax_kernel(const float* __restrict__ S, bf16* __restrict__ Ph, bf16* __restrict__ Pl)
{
    const float* row = S + (size_t)blockIdx.x * S_;
    const int tid = threadIdx.x;
    float v[8];
#pragma unroll
    for (int k = 0; k < 8; k++) v[k] = row[tid + k * 256];
    float m = v[0];
#pragma unroll
    for (int k = 1; k < 8; k++) m = fmaxf(m, v[k]);
#pragma unroll
    for (int o = 16; o; o >>= 1) m = fmaxf(m, __shfl_xor_sync(0xffffffffu, m, o));
    __shared__ float red[8];
    if ((tid & 31) == 0) red[tid >> 5] = m;
    __syncthreads();
    float mm = red[0];
#pragma unroll
    for (int w = 1; w < 8; w++) mm = fmaxf(mm, red[w]);
    __syncthreads();
    float s = 0.f;
#pragma unroll
    for (int k = 0; k < 8; k++) { v[k] = __expf(v[k] - mm); s += v[k]; }
#pragma unroll
    for (int o = 16; o; o >>= 1) s += __shfl_xor_sync(0xffffffffu, s, o);
    if ((tid & 31) == 0) red[tid >> 5] = s;
    __syncthreads();
    float tot = red[0];
#pragma unroll
    for (int w = 1; w < 8; w++) tot += red[w];
    const float inv = 1.f / tot;
    const size_t base = (size_t)blockIdx.x * S_;
#pragma unroll
    for (int k = 0; k < 8; k++) {
        bf16 hi, lo; splitf(v[k] * inv, hi, lo);
        Ph[base + tid + k * 256] = hi;
        Pl[base + tid + k * 256] = lo;
    }
}

// ---------------- Host launch ----------------
static inline void launch_gemm(const bf16* Ah, const bf16* Al,
                               const bf16* Bh, const bf16* Bl, float* C,
                               int M, int N, int K, int lda, int ldb, int ldc,
                               long long aSb, long long aSh, long long bSb, long long bSh,
                               long long cSb, long long cSh, int gz, float alpha)
{
    dim3 grid((N + 127) / 128, (M + 127) / 128, gz);
    mma_gemm<<<grid, 256, GEMM_SMEM>>>(Ah, Al, Bh, Bl, C, M, N, K, lda, ldb, ldc,
                                       aSb, aSh, bSb, bSh, cSb, cSh, alpha);
}

extern "C" void kernel_launch(void* const* d_in, const int* in_sizes, int n_in,
                              void* d_out, int out_size)
{
    (void)in_sizes; (void)n_in; (void)out_size;
    const float* hidden    = (const float*)d_in[0];
    const float* wq_a      = (const float*)d_in[1];
    const float* q_norm_w  = (const float*)d_in[2];
    const float* wq_b      = (const float*)d_in[3];
    const float* wkv_a     = (const float*)d_in[4];
    const float* kv_norm_w = (const float*)d_in[5];
    const float* wkv_b     = (const float*)d_in[6];
    const float* wo        = (const float*)d_in[7];
    float* out = (float*)d_out;

    cudaFuncSetAttribute(mma_gemm, cudaFuncAttributeMaxDynamicSharedMemorySize, GEMM_SMEM);

    float *qlat, *kva, *q, *kvx, *scores, *attn;
    cudaGetSymbolAddress((void**)&qlat,   g_qlat);
    cudaGetSymbolAddress((void**)&kva,    g_kva);
    cudaGetSymbolAddress((void**)&q,      g_q);
    cudaGetSymbolAddress((void**)&kvx,    g_kvx);
    cudaGetSymbolAddress((void**)&scores, g_scores);
    cudaGetSymbolAddress((void**)&attn,   g_attn);

    bf16 *hid_h, *hid_l, *wqa_h, *wqa_l, *wqb_h, *wqb_l, *wkva_h, *wkva_l;
    bf16 *wkvb_h, *wkvb_l, *wo_h, *wo_l, *qlat_h, *qlat_l, *kva_h, *kva_l;
    bf16 *qs_h, *qs_l, *kf_h, *kf_l, *P_h, *P_l, *vt_h, *vt_l, *attn_h, *attn_l;
    cudaGetSymbolAddress((void**)&hid_h,  g_hid_h);  cudaGetSymbolAddress((void**)&hid_l,  g_hid_l);
    cudaGetSymbolAddress((void**)&wqa_h,  g_wqa_h);  cudaGetSymbolAddress((void**)&wqa_l,  g_wqa_l);
    cudaGetSymbolAddress((void**)&wqb_h,  g_wqb_h);  cudaGetSymbolAddress((void**)&wqb_l,  g_wqb_l);
    cudaGetSymbolAddress((void**)&wkva_h, g_wkva_h); cudaGetSymbolAddress((void**)&wkva_l, g_wkva_l);
    cudaGetSymbolAddress((void**)&wkvb_h, g_wkvb_h); cudaGetSymbolAddress((void**)&wkvb_l, g_wkvb_l);
    cudaGetSymbolAddress((void**)&wo_h,   g_wo_h);   cudaGetSymbolAddress((void**)&wo_l,   g_wo_l);
    cudaGetSymbolAddress((void**)&qlat_h, g_qlat_h); cudaGetSymbolAddress((void**)&qlat_l, g_qlat_l);
    cudaGetSymbolAddress((void**)&kva_h,  g_kva_h);  cudaGetSymbolAddress((void**)&kva_l,  g_kva_l);
    cudaGetSymbolAddress((void**)&qs_h,   g_qs_h);   cudaGetSymbolAddress((void**)&qs_l,   g_qs_l);
    cudaGetSymbolAddress((void**)&kf_h,   g_kf_h);   cudaGetSymbolAddress((void**)&kf_l,   g_kf_l);
    cudaGetSymbolAddress((void**)&P_h,    g_P_h);    cudaGetSymbolAddress((void**)&P_l,    g_P_l);
    cudaGetSymbolAddress((void**)&vt_h,   g_vt_h);   cudaGetSymbolAddress((void**)&vt_l,   g_vt_l);
    cudaGetSymbolAddress((void**)&attn_h, g_attn_h); cudaGetSymbolAddress((void**)&attn_l, g_attn_l);

    const float SCALE = (float)(1.0 / sqrt((double)DQK));

    freqs_kernel<<<S_, 32>>>();

    // split inputs / weights
    launch_split(hidden, hid_h, hid_l, (long long)BS_ * H_);
    launch_split(wq_a,   wqa_h, wqa_l, (long long)QL * H_);
    launch_split(wq_b,   wqb_h, wqb_l, (long long)NH_ * DQK * QL);
    launch_split(wkv_a,  wkva_h, wkva_l, (long long)(KVL + DR) * H_);
    launch_split(wkv_b,  wkvb_h, wkvb_l, (long long)NH_ * (DN + DV) * KVL);
    launch_split(wo,     wo_h,  wo_l,  (long long)H_ * NH_ * DV);

    // 1) q_lat = hidden @ wq_a^T       [4096, 1536], K=2048
    launch_gemm(hid_h, hid_l, wqa_h, wqa_l, qlat, BS_, QL, H_,
                H_, H_, QL, 0,0,0,0,0,0, 1, 1.f);
    // 2) kva = hidden @ wkv_a^T        [4096, 576], K=2048
    launch_gemm(hid_h, hid_l, wkva_h, wkva_l, kva, BS_, KVL + DR, H_,
                H_, H_, KVL + DR, 0,0,0,0,0,0, 1, 1.f);
    // 3/4) rmsnorms
    rmsnorm_kernel<<<BS_, 256>>>(qlat, q_norm_w, QL, QL);
    rmsnorm_kernel<<<BS_, 256>>>(kva, kv_norm_w, KVL, KVL + DR);
    // 5) RoPE k_pe
    rope_k_kernel<<<BS_, 32>>>(kva);
    // splits of normalized activations
    launch_split(qlat, qlat_h, qlat_l, (long long)BS_ * QL);
    launch_split(kva,  kva_h,  kva_l,  (long long)BS_ * (KVL + DR));
    // 6) q = q_lat @ wq_b^T            [4096, 3072], K=1536
    launch_gemm(qlat_h, qlat_l, wqb_h, wqb_l, q, BS_, NH_ * DQK, QL,
                QL, QL, NH_ * DQK, 0,0,0,0,0,0, 1, 1.f);
    // 7) kv_x = kv_c @ wkv_b^T         [4096, 4096], K=512 (A row stride 576)
    launch_gemm(kva_h, kva_l, wkvb_h, wkvb_l, kvx, BS_, NH_ * (DN + DV), KVL,
                KVL + DR, KVL, NH_ * (DN + DV), 0,0,0,0,0,0, 1, 1.f);
    // 8) RoPE q_pe, then split q
    rope_q_kernel<<<BS_, 512>>>(q);
    launch_split(q, qs_h, qs_l, (long long)BS_ * NH_ * DQK);
    // 9) assemble kf (split out)
    build_kf_kernel<<<BS_, 256>>>(kvx, kva, kf_h, kf_l);
    // 10) V^T (split out)
    {
        dim3 grid(S_ / 32, DV / 32, B_ * NH_);
        transpose_v_kernel<<<grid, dim3(32, 8)>>>(kvx, vt_h, vt_l);
    }
    // 11) scores = SCALE * q . kf^T, batched z = b*16+h   [2048x2048, K=192]
    launch_gemm(qs_h, qs_l, kf_h, kf_l, scores, S_, S_, DQK,
                NH_ * DQK, NH_ * DQK, S_,
                (long long)S_ * NH_ * DQK, DQK,
                (long long)S_ * NH_ * DQK, DQK,
                (long long)NH_ * S_ * S_, (long long)S_ * S_,
                B_ * NH_, SCALE);
    // 12) softmax rows -> split P
    softmax_kernel<<<B_ * NH_ * S_, 256>>>(scores, P_h, P_l);
    // 13) attn = P @ vt^T, batched      [2048x128, K=2048]
    launch_gemm(P_h, P_l, vt_h, vt_l, attn, S_, DV, S_,
                S_, S_, NH_ * DV,
                (long long)NH_ * S_ * S_, (long long)S_ * S_,
                (long long)NH_ * DV * S_, (long long)DV * S_,
                (long long)S_ * NH_ * DV, (long long)DV,
                B_ * NH_, 1.f);
    // split attn
    launch_split(attn, attn_h, attn_l, (long long)BS_ * NH_ * DV);
    // 14) out = attn @ wo^T            [4096, 2048], K=2048
    launch_gemm(attn_h, attn_l, wo_h, wo_l, out, BS_, H_, NH_ * DV,
                NH_ * DV, NH_ * DV, H_, 0,0,0,0,0,0, 1, 1.f);
}